// round 16
// baseline (speedup 1.0000x reference)
#include <cuda_runtime.h>
#include <cuda_fp16.h>
#include <math.h>
#include <stdint.h>

#define T    2048
#define D    1024
#define E    16
#define KSEL 4
#define NG   4
#define EPG  4
#define F    1024
#define SHF  2048
#define SCALEF 2.5f

// ---------------- scratch ------------------------------------------------------
__device__ int    g_cnt[E];
__device__ int    g_tok[E * T];
__device__ float  g_wt [E * T];
__device__ __half g_xh  [(size_t)T * D];         // x, fp16
__device__ __half g_gwh [(size_t)E * D * F];     // gate_w fp16, ORIGINAL layout
__device__ __half g_uwh [(size_t)E * D * F];     // up_w   fp16
__device__ __half g_dwh [(size_t)E * F * D];     // down_w fp16
__device__ __half g_shgh[(size_t)D * SHF];       // sh_gate fp16
__device__ __half g_shuh[(size_t)D * SHF];       // sh_up   fp16
__device__ __half g_shdh[(size_t)SHF * D];       // sh_down fp16
__device__ __half g_act [(size_t)E * T * F];     // routed silu(g)*u fp16
__device__ __half g_shact[(size_t)T * SHF];      // shared silu(g)*u fp16

// ---------------- helpers ------------------------------------------------------
__device__ __forceinline__ uint32_t su32(const void* p) {
    uint32_t a;
    asm("{ .reg .u64 t; cvta.to.shared.u64 t, %1; cvt.u32.u64 %0, t; }"
        : "=r"(a) : "l"(p));
    return a;
}
__device__ __forceinline__ float silu(float g) { return g / (1.f + expf(-g)); }

__device__ __forceinline__ void cph16(void* sdst, const void* gsrc) {
    asm volatile("cp.async.cg.shared.global [%0], [%1], 16;"
                 :: "r"(su32(sdst)), "l"(gsrc));
}
#define CP_COMMIT() asm volatile("cp.async.commit_group;" ::: "memory")
#define CP_WAIT1()  asm volatile("cp.async.wait_group 1;" ::: "memory")

__device__ __forceinline__ void mma_f16(float c[4], const uint32_t a[4],
                                        const uint32_t b[2]) {
    asm volatile(
        "mma.sync.aligned.m16n8k16.row.col.f32.f16.f16.f32 "
        "{%0,%1,%2,%3}, {%4,%5,%6,%7}, {%8,%9}, {%0,%1,%2,%3};"
        : "+f"(c[0]), "+f"(c[1]), "+f"(c[2]), "+f"(c[3])
        : "r"(a[0]), "r"(a[1]), "r"(a[2]), "r"(a[3]), "r"(b[0]), "r"(b[1]));
}

__device__ __forceinline__ void ldm_x4(uint32_t& r0, uint32_t& r1,
                                       uint32_t& r2, uint32_t& r3, uint32_t addr) {
    asm volatile("ldmatrix.sync.aligned.m8n8.x4.shared.b16 {%0,%1,%2,%3}, [%4];"
                 : "=r"(r0), "=r"(r1), "=r"(r2), "=r"(r3) : "r"(addr));
}
__device__ __forceinline__ void ldm_x4t(uint32_t& r0, uint32_t& r1,
                                        uint32_t& r2, uint32_t& r3, uint32_t addr) {
    asm volatile("ldmatrix.sync.aligned.m8n8.x4.trans.shared.b16 {%0,%1,%2,%3}, [%4];"
                 : "=r"(r0), "=r"(r1), "=r"(r2), "=r"(r3) : "r"(addr));
}

// A smem: row-major [128][ALDH], ALDH=72 halfs (144B): 8-row phases cover 32 banks.
// B smem: k-major [64][BLDH]; BLDH=136 (gateup,128n) / 264 (down,256n):
//   row shift = 4 words -> 8-row trans-ldmatrix phases cover all 32 banks.
#define ALDH 72
#define GBLD 136
#define DBLD 264

#define GU_SMEM (2 * (128 * ALDH + 2 * 64 * GBLD) * 2)   // 106496 B
#define DN_SMEM (2 * (128 * ALDH + 64 * DBLD) * 2)       // 104448 B

// ================= fused gate+up GEMM (tile 128x128, BK=64, 512 thr) ==========
template <bool GATHER>
__global__ void __launch_bounds__(512, 1)
gateup_mma(const __half* __restrict__ A, const __half* __restrict__ Bg,
           const __half* __restrict__ Bu, __half* __restrict__ Oact,
           size_t b_exp_stride, int BN, int ostride, int use_expert) {
    const int e   = use_expert ? blockIdx.z : 0;
    const int cnt = use_expert ? g_cnt[e] : T;
    const int m0  = blockIdx.y * 128;
    if (m0 >= cnt) return;
    const int n0  = blockIdx.x * 128;

    extern __shared__ __half sm[];
    __half* AS  = sm;                            // [2][128*ALDH]
    __half* BGS = sm + 2 * 128 * ALDH;           // [2][64*GBLD]
    __half* BUS = BGS + 2 * 64 * GBLD;           // [2][64*GBLD]
    __shared__ int rows[128];

    const int tid  = threadIdx.x;
    const int lane = tid & 31;
    const int wid  = tid >> 5;
    const int warp_m = wid & 3;
    const int warp_n = wid >> 2;

    if (tid < 128) {
        if (GATHER) {
            int i = m0 + tid;
            rows[tid] = g_tok[e * T + (i < cnt ? i : cnt - 1)];
        } else {
            rows[tid] = m0 + tid;
        }
    }
    __syncthreads();

    // A fill: 128 rows x 64 halfs; thread -> (row=tid>>2, kc=(tid&3)*8), chunks {0,32}
    const int aRow = tid >> 2, aKc = (tid & 3) * 8;
    const __half* aG = A + (size_t)rows[aRow] * D + aKc;
    const int aOffS = aRow * ALDH + aKc;

    // B fill: 64 k-rows x 128 n; thread -> (krow=tid>>3, nc=(tid&7)*8), chunks {0,64}
    const int bRow = tid >> 3, bCol = (tid & 7) * 8;
    const __half* bgG = Bg + (use_expert ? (size_t)e * b_exp_stride : 0) +
                        (size_t)bRow * BN + n0 + bCol;
    const __half* buG = Bu + (use_expert ? (size_t)e * b_exp_stride : 0) +
                        (size_t)bRow * BN + n0 + bCol;
    const int bOffS = bRow * GBLD + bCol;

    const uint32_t aSm  = su32(AS);
    const uint32_t bgSm = su32(BGS);
    const uint32_t buSm = su32(BUS);
    uint32_t aOff[2], bOff[2];
#pragma unroll
    for (int mt = 0; mt < 2; mt++)
        aOff[mt] = ((warp_m * 32 + mt * 16 + (lane & 15)) * ALDH +
                    (lane >> 4) * 8) * 2;
#pragma unroll
    for (int p = 0; p < 2; p++)   // trans: row = k (lane&15), col = n
        bOff[p] = ((lane & 15) * GBLD +
                   warp_n * 32 + p * 16 + (lane >> 4) * 8) * 2;

    float ag[2][4][4], au[2][4][4];
#pragma unroll
    for (int mt = 0; mt < 2; mt++)
#pragma unroll
        for (int nt = 0; nt < 4; nt++)
#pragma unroll
            for (int j = 0; j < 4; j++) { ag[mt][nt][j] = 0.f; au[mt][nt][j] = 0.f; }

    {   // stage 0 (k 0..63)
        cph16(&AS[aOffS], aG);            cph16(&AS[aOffS + 32], aG + 32);
        cph16(&BGS[bOffS], bgG);          cph16(&BGS[bOffS + 64], bgG + 64);
        cph16(&BUS[bOffS], buG);          cph16(&BUS[bOffS + 64], buG + 64);
    }
    CP_COMMIT();

    int buf = 0;
    for (int k0 = 0; k0 < D; k0 += 64) {
        if (k0 + 64 < D) {
            int s = buf ^ 1;
            const int ao = s * 128 * ALDH, bo = s * 64 * GBLD;
            const __half* ap = aG + k0 + 64;
            cph16(&AS[ao + aOffS], ap);
            cph16(&AS[ao + aOffS + 32], ap + 32);
            const __half* gp = bgG + (size_t)(k0 + 64) * BN;
            cph16(&BGS[bo + bOffS], gp);
            cph16(&BGS[bo + bOffS + 64], gp + 64);
            const __half* up = buG + (size_t)(k0 + 64) * BN;
            cph16(&BUS[bo + bOffS], up);
            cph16(&BUS[bo + bOffS + 64], up + 64);
        }
        CP_COMMIT();
        CP_WAIT1();
        __syncthreads();

        const uint32_t aB  = aSm  + buf * (128 * ALDH * 2);
        const uint32_t bgB = bgSm + buf * (64 * GBLD * 2);
        const uint32_t buB = buSm + buf * (64 * GBLD * 2);
#pragma unroll
        for (int ks = 0; ks < 4; ks++) {
            const uint32_t kA = ks * 32;                 // 16 halfs along A row
            const uint32_t kB = ks * 16 * GBLD * 2;      // 16 k-rows in B
            uint32_t af[2][4], bfg[4][2], bfu[4][2];
#pragma unroll
            for (int mt = 0; mt < 2; mt++)
                ldm_x4(af[mt][0], af[mt][1], af[mt][2], af[mt][3],
                       aB + aOff[mt] + kA);
#pragma unroll
            for (int p = 0; p < 2; p++) {
                ldm_x4t(bfg[2 * p][0], bfg[2 * p][1], bfg[2 * p + 1][0],
                        bfg[2 * p + 1][1], bgB + bOff[p] + kB);
                ldm_x4t(bfu[2 * p][0], bfu[2 * p][1], bfu[2 * p + 1][0],
                        bfu[2 * p + 1][1], buB + bOff[p] + kB);
            }
#pragma unroll
            for (int mt = 0; mt < 2; mt++)
#pragma unroll
                for (int nt = 0; nt < 4; nt++) {
                    mma_f16(ag[mt][nt], af[mt], bfg[nt]);
                    mma_f16(au[mt][nt], af[mt], bfu[nt]);
                }
        }
        __syncthreads();
        buf ^= 1;
    }

#pragma unroll
    for (int mt = 0; mt < 2; mt++) {
#pragma unroll
        for (int half = 0; half < 2; half++) {
            const int m = m0 + warp_m * 32 + mt * 16 + (lane >> 2) + half * 8;
            if (m >= cnt) continue;
            __half* orow = use_expert
                ? Oact + ((size_t)e * T + m) * ostride + n0
                : Oact + (size_t)m * ostride + n0;
#pragma unroll
            for (int nt = 0; nt < 4; nt++) {
                const int c = warp_n * 32 + nt * 8 + 2 * (lane & 3);
                float g0 = ag[mt][nt][half * 2 + 0], u0 = au[mt][nt][half * 2 + 0];
                float g1 = ag[mt][nt][half * 2 + 1], u1 = au[mt][nt][half * 2 + 1];
                __half2 o = __floats2half2_rn(silu(g0) * u0, silu(g1) * u1);
                *(__half2*)(orow + c) = o;
            }
        }
    }
}

// ================= down GEMM (tile 128x256, BK=64, 512 thr) ===================
#define EPI_STORE  2
#define EPI_ATOMIC 3

template <int MODE>
__global__ void __launch_bounds__(512, 1)
down_mma(const __half* __restrict__ A, const __half* __restrict__ B,
         float* __restrict__ O, int K, size_t b_exp_stride, int use_expert) {
    const int e   = use_expert ? blockIdx.z : 0;
    const int cnt = use_expert ? g_cnt[e] : T;
    const int m0  = blockIdx.y * 128;
    if (m0 >= cnt) return;
    const int n0  = blockIdx.x * 256;

    extern __shared__ __half sm[];
    __half* AS = sm;                            // [2][128*ALDH]
    __half* BS = sm + 2 * 128 * ALDH;           // [2][64*DBLD]

    const int tid  = threadIdx.x;
    const int lane = tid & 31;
    const int wid  = tid >> 5;
    const int warp_m = wid & 3;
    const int warp_n = wid >> 2;

    // A fill: (row=tid>>2, kc=(tid&3)*8), chunks {0,32}
    const int aRow = tid >> 2, aKc = (tid & 3) * 8;
    const int aOffS = aRow * ALDH + aKc;
    const __half* aG = A + (use_expert ? (size_t)e * T * K : 0) +
                       (size_t)(m0 + aRow) * K + aKc;

    // B fill: 64 k-rows x 256 n; thread -> (krow=tid>>3, nc=(tid&7)*8), 4 chunks
    const int bRow = tid >> 3, bCol = (tid & 7) * 8;
    const int bOffS = bRow * DBLD + bCol;
    const __half* bG = B + (use_expert ? (size_t)e * b_exp_stride : 0) +
                       (size_t)bRow * D + n0 + bCol;

    const uint32_t aSm = su32(AS);
    const uint32_t bSm = su32(BS);
    uint32_t aOff[2], bOff[4];
#pragma unroll
    for (int mt = 0; mt < 2; mt++)
        aOff[mt] = ((warp_m * 32 + mt * 16 + (lane & 15)) * ALDH +
                    (lane >> 4) * 8) * 2;
#pragma unroll
    for (int p = 0; p < 4; p++)
        bOff[p] = ((lane & 15) * DBLD +
                   warp_n * 64 + p * 16 + (lane >> 4) * 8) * 2;

    float acc[2][8][4];
#pragma unroll
    for (int mt = 0; mt < 2; mt++)
#pragma unroll
        for (int nt = 0; nt < 8; nt++)
#pragma unroll
            for (int j = 0; j < 4; j++) acc[mt][nt][j] = 0.f;

    {
        cph16(&AS[aOffS], aG);               cph16(&AS[aOffS + 32], aG + 32);
        cph16(&BS[bOffS], bG);               cph16(&BS[bOffS + 64], bG + 64);
        cph16(&BS[bOffS + 128], bG + 128);   cph16(&BS[bOffS + 192], bG + 192);
    }
    CP_COMMIT();

    int buf = 0;
    for (int k0 = 0; k0 < K; k0 += 64) {
        if (k0 + 64 < K) {
            int s = buf ^ 1;
            const int ao = s * 128 * ALDH, bo = s * 64 * DBLD;
            const __half* ap = aG + k0 + 64;
            cph16(&AS[ao + aOffS], ap);
            cph16(&AS[ao + aOffS + 32], ap + 32);
            const __half* bp = bG + (size_t)(k0 + 64) * D;
            cph16(&BS[bo + bOffS], bp);
            cph16(&BS[bo + bOffS + 64], bp + 64);
            cph16(&BS[bo + bOffS + 128], bp + 128);
            cph16(&BS[bo + bOffS + 192], bp + 192);
        }
        CP_COMMIT();
        CP_WAIT1();
        __syncthreads();

        const uint32_t aB = aSm + buf * (128 * ALDH * 2);
        const uint32_t bB = bSm + buf * (64 * DBLD * 2);
#pragma unroll
        for (int ks = 0; ks < 4; ks++) {
            const uint32_t kA = ks * 32;
            const uint32_t kB = ks * 16 * DBLD * 2;
            uint32_t af[2][4], bf[8][2];
#pragma unroll
            for (int mt = 0; mt < 2; mt++)
                ldm_x4(af[mt][0], af[mt][1], af[mt][2], af[mt][3],
                       aB + aOff[mt] + kA);
#pragma unroll
            for (int p = 0; p < 4; p++)
                ldm_x4t(bf[2 * p][0], bf[2 * p][1], bf[2 * p + 1][0],
                        bf[2 * p + 1][1], bB + bOff[p] + kB);
#pragma unroll
            for (int mt = 0; mt < 2; mt++)
#pragma unroll
                for (int nt = 0; nt < 8; nt++)
                    mma_f16(acc[mt][nt], af[mt], bf[nt]);
        }
        __syncthreads();
        buf ^= 1;
    }

#pragma unroll
    for (int mt = 0; mt < 2; mt++) {
#pragma unroll
        for (int half = 0; half < 2; half++) {
            const int m = m0 + warp_m * 32 + mt * 16 + (lane >> 2) + half * 8;
            if (m >= cnt) continue;
            int   tok = m;
            float w   = 1.f;
            if (MODE == EPI_ATOMIC) { tok = g_tok[e * T + m]; w = g_wt[e * T + m]; }
            float* orow = O + (size_t)tok * D + n0;
#pragma unroll
            for (int nt = 0; nt < 8; nt++) {
                const int c = warp_n * 64 + nt * 8 + 2 * (lane & 3);
                float v0 = acc[mt][nt][half * 2 + 0];
                float v1 = acc[mt][nt][half * 2 + 1];
                if (MODE == EPI_STORE) {
                    float2 o = {v0, v1};
                    *(float2*)(orow + c) = o;
                } else {
                    atomicAdd(orow + c,     w * v0);
                    atomicAdd(orow + c + 1, w * v1);
                }
            }
        }
    }
}

// ---------------- prep kernels --------------------------------------------------
__global__ void zero_cnt_kernel() {
    if (threadIdx.x < E) g_cnt[threadIdx.x] = 0;
}

__global__ void cvtx_kernel(const float* __restrict__ x) {
    size_t i = ((size_t)blockIdx.x * 256 + threadIdx.x) * 4;
    float4 v = *(const float4*)(x + i);
    __half2 h0 = __floats2half2_rn(v.x, v.y);
    __half2 h1 = __floats2half2_rn(v.z, v.w);
    *(__half2*)(g_xh + i)     = h0;
    *(__half2*)(g_xh + i + 2) = h1;
}

// streaming fp32 -> fp16 convert for 3 equal-size tensors (z selects)
__global__ void cvtw3_kernel(const float* __restrict__ s0, const float* __restrict__ s1,
                             const float* __restrict__ s2, __half* __restrict__ d0,
                             __half* __restrict__ d1, __half* __restrict__ d2) {
    const int z = blockIdx.y;
    const float* s = (z == 0) ? s0 : (z == 1) ? s1 : s2;
    __half*      d = (z == 0) ? d0 : (z == 1) ? d1 : d2;
    size_t i = ((size_t)blockIdx.x * 256 + threadIdx.x) * 4;
    float4 v = *(const float4*)(s + i);
    __half2 h0 = __floats2half2_rn(v.x, v.y);
    __half2 h1 = __floats2half2_rn(v.z, v.w);
    uint2 o = {*(uint32_t*)&h0, *(uint32_t*)&h1};
    *(uint2*)(d + i) = o;
}

// ---------------- router (fp32, bit-exact routing) ------------------------------
__global__ void router_kernel(const float* __restrict__ x,
                              const float* __restrict__ rw,
                              const float* __restrict__ bias) {
    int t    = blockIdx.x * (blockDim.x >> 5) + (threadIdx.x >> 5);
    int lane = threadIdx.x & 31;
    if (t >= T) return;
    const float4* xr = (const float4*)(x + (size_t)t * D);

    float logit[E];
#pragma unroll
    for (int e = 0; e < E; e++) {
        const float4* w = (const float4*)(rw + (size_t)e * D);
        float p = 0.f;
        for (int k = lane; k < D / 4; k += 32) {
            float4 a = xr[k], b = w[k];
            p += a.x * b.x + a.y * b.y + a.z * b.z + a.w * b.w;
        }
#pragma unroll
        for (int o = 16; o > 0; o >>= 1) p += __shfl_xor_sync(0xffffffffu, p, o);
        logit[e] = p;
    }

    if (lane == 0) {
        float scores[E], s[E];
#pragma unroll
        for (int e = 0; e < E; e++) {
            scores[e] = 1.f / (1.f + expf(-logit[e]));
            s[e]      = scores[e] + bias[e];
        }
        float gs[NG];
#pragma unroll
        for (int g = 0; g < NG; g++) {
            float m1 = -1e30f, m2 = -1e30f;
#pragma unroll
            for (int j = 0; j < EPG; j++) {
                float v = s[g * EPG + j];
                if (v > m1) { m2 = m1; m1 = v; }
                else if (v > m2) { m2 = v; }
            }
            gs[g] = m1 + m2;
        }
        int g1 = 0; float b1 = -1e30f;
#pragma unroll
        for (int g = 0; g < NG; g++) if (gs[g] > b1) { b1 = gs[g]; g1 = g; }
        int g2 = -1; float b2 = -1e30f;
#pragma unroll
        for (int g = 0; g < NG; g++) if (g != g1 && gs[g] > b2) { b2 = gs[g]; g2 = g; }

        float masked[E];
#pragma unroll
        for (int e = 0; e < E; e++) {
            int g = e / EPG;
            masked[e] = (g == g1 || g == g2) ? s[e] : -1.0f;
        }
        int idx[KSEL]; bool taken[E];
#pragma unroll
        for (int e = 0; e < E; e++) taken[e] = false;
#pragma unroll
        for (int k = 0; k < KSEL; k++) {
            float best = -1e30f; int bi = 0;
#pragma unroll
            for (int e = 0; e < E; e++)
                if (!taken[e] && masked[e] > best) { best = masked[e]; bi = e; }
            taken[bi] = true;
            idx[k] = bi;
        }
        float tw[KSEL], sum = 0.f;
#pragma unroll
        for (int k = 0; k < KSEL; k++) { tw[k] = scores[idx[k]]; sum += tw[k]; }
        float inv = SCALEF / (sum + 1e-20f);
#pragma unroll
        for (int k = 0; k < KSEL; k++) {
            int e = idx[k];
            int pos = atomicAdd(&g_cnt[e], 1);
            g_tok[e * T + pos] = t;
            g_wt [e * T + pos] = tw[k] * inv;
        }
    }
}

// ---------------- launch --------------------------------------------------------
extern "C" void kernel_launch(void* const* d_in, const int* in_sizes, int n_in,
                              void* d_out, int out_size) {
    const float* x      = (const float*)d_in[0];
    const float* rw     = (const float*)d_in[1];
    const float* bias   = (const float*)d_in[2];
    const float* gate_w = (const float*)d_in[3];   // [E][D][F]
    const float* up_w   = (const float*)d_in[4];   // [E][D][F]
    const float* down_w = (const float*)d_in[5];   // [E][F][D]
    const float* shg    = (const float*)d_in[6];   // [D][SHF]
    const float* shu    = (const float*)d_in[7];   // [D][SHF]
    const float* shd    = (const float*)d_in[8];   // [SHF][D]
    float* out = (float*)d_out;

    __half *p_xh, *p_gwh, *p_uwh, *p_dwh, *p_shgh, *p_shuh, *p_shdh, *p_act, *p_shact;
    cudaGetSymbolAddress((void**)&p_xh,    g_xh);
    cudaGetSymbolAddress((void**)&p_gwh,   g_gwh);
    cudaGetSymbolAddress((void**)&p_uwh,   g_uwh);
    cudaGetSymbolAddress((void**)&p_dwh,   g_dwh);
    cudaGetSymbolAddress((void**)&p_shgh,  g_shgh);
    cudaGetSymbolAddress((void**)&p_shuh,  g_shuh);
    cudaGetSymbolAddress((void**)&p_shdh,  g_shdh);
    cudaGetSymbolAddress((void**)&p_act,   g_act);
    cudaGetSymbolAddress((void**)&p_shact, g_shact);

    cudaFuncSetAttribute(gateup_mma<true>,
                         cudaFuncAttributeMaxDynamicSharedMemorySize, GU_SMEM);
    cudaFuncSetAttribute(gateup_mma<false>,
                         cudaFuncAttributeMaxDynamicSharedMemorySize, GU_SMEM);
    cudaFuncSetAttribute(down_mma<EPI_STORE>,
                         cudaFuncAttributeMaxDynamicSharedMemorySize, DN_SMEM);
    cudaFuncSetAttribute(down_mma<EPI_ATOMIC>,
                         cudaFuncAttributeMaxDynamicSharedMemorySize, DN_SMEM);

    // launch index 5 = routed gateup (ncu -s 5 profiles the GEMM)
    zero_cnt_kernel<<<1, 32>>>();                                        // 0
    router_kernel<<<T / 8, 256>>>(x, rw, bias);                          // 1
    cvtx_kernel<<<(T * D) / 1024, 256>>>(x);                             // 2
    cvtw3_kernel<<<dim3((E * D * F) / 1024, 3), 256>>>(                  // 3
        gate_w, up_w, down_w, p_gwh, p_uwh, p_dwh);
    cvtw3_kernel<<<dim3((D * SHF) / 1024, 3), 256>>>(                    // 4
        shg, shu, shd, p_shgh, p_shuh, p_shdh);
    gateup_mma<true><<<dim3(F / 128, T / 128, E), 512, GU_SMEM>>>(       // 5
        p_xh, p_gwh, p_uwh, p_act, (size_t)D * F, F, F, 1);
    gateup_mma<false><<<dim3(SHF / 128, T / 128, 1), 512, GU_SMEM>>>(
        p_xh, p_shgh, p_shuh, p_shact, 0, SHF, SHF, 0);
    down_mma<EPI_STORE><<<dim3(D / 256, T / 128, 1), 512, DN_SMEM>>>(
        p_shact, p_shdh, out, SHF, 0, 0);
    down_mma<EPI_ATOMIC><<<dim3(D / 256, T / 128, E), 512, DN_SMEM>>>(
        p_act, p_dwh, out, F, (size_t)F * D, 1);
}

// round 17
// speedup vs baseline: 1.3166x; 1.3166x over previous
#include <cuda_runtime.h>
#include <cuda_fp16.h>
#include <math.h>
#include <stdint.h>

#define T    2048
#define D    1024
#define E    16
#define KSEL 4
#define NG   4
#define EPG  4
#define F    1024
#define SHF  2048
#define SCALEF 2.5f

// ---------------- scratch ------------------------------------------------------
__device__ int    g_cnt[E];
__device__ int    g_tok[E * T];
__device__ float  g_wt [E * T];
__device__ __half g_xh  [(size_t)T * D];
__device__ __half g_gwT [(size_t)E * F * D];     // gate_w n-major [E][F][D] fp16
__device__ __half g_uwT [(size_t)E * F * D];     // up_w   n-major
__device__ __half g_dwT [(size_t)E * D * F];     // down_w n-major [E][D][F]
__device__ __half g_shgT[(size_t)SHF * D];
__device__ __half g_shuT[(size_t)SHF * D];
__device__ __half g_shdT[(size_t)D * SHF];
__device__ __half g_act [(size_t)E * T * F];
__device__ __half g_shact[(size_t)T * SHF];

// ---------------- helpers ------------------------------------------------------
__device__ __forceinline__ uint32_t su32(const void* p) {
    uint32_t a;
    asm("{ .reg .u64 t; cvta.to.shared.u64 t, %1; cvt.u32.u64 %0, t; }"
        : "=r"(a) : "l"(p));
    return a;
}
__device__ __forceinline__ float silu(float g) { return g / (1.f + expf(-g)); }

__device__ __forceinline__ void cph16(void* sdst, const void* gsrc) {
    asm volatile("cp.async.cg.shared.global [%0], [%1], 16;"
                 :: "r"(su32(sdst)), "l"(gsrc));
}
#define CP_COMMIT() asm volatile("cp.async.commit_group;" ::: "memory")
#define CP_WAIT1()  asm volatile("cp.async.wait_group 1;" ::: "memory")

__device__ __forceinline__ void mma_f16(float c[4], const uint32_t a[4],
                                        const uint32_t b[2]) {
    asm volatile(
        "mma.sync.aligned.m16n8k16.row.col.f32.f16.f16.f32 "
        "{%0,%1,%2,%3}, {%4,%5,%6,%7}, {%8,%9}, {%0,%1,%2,%3};"
        : "+f"(c[0]), "+f"(c[1]), "+f"(c[2]), "+f"(c[3])
        : "r"(a[0]), "r"(a[1]), "r"(a[2]), "r"(a[3]), "r"(b[0]), "r"(b[1]));
}

__device__ __forceinline__ void ldm_x4(uint32_t& r0, uint32_t& r1,
                                       uint32_t& r2, uint32_t& r3, uint32_t addr) {
    asm volatile("ldmatrix.sync.aligned.m8n8.x4.shared.b16 {%0,%1,%2,%3}, [%4];"
                 : "=r"(r0), "=r"(r1), "=r"(r2), "=r"(r3) : "r"(addr));
}

// BK=64: 72-half rows (144B), ldmatrix 8-row phases conflict-free & 16B-aligned.
#define HLD 72

#define GU_SMEM (2 * (3 * 128) * HLD * 2)   // 110592 B
#define DN_SMEM (2 * (128 + 256) * HLD * 2) // 110592 B

// ================= fused gate+up GEMM (tile 128x128, BK=64, 512 thr) ==========
template <bool GATHER>
__global__ void __launch_bounds__(512, 1)
gateup_mma(const __half* __restrict__ A, const __half* __restrict__ Bg,
           const __half* __restrict__ Bu, __half* __restrict__ Oact,
           size_t b_exp_stride, int ostride, int use_expert) {
    const int e   = use_expert ? blockIdx.z : 0;
    const int cnt = use_expert ? g_cnt[e] : T;
    const int m0  = blockIdx.y * 128;
    if (m0 >= cnt) return;
    const int n0  = blockIdx.x * 128;

    extern __shared__ __half sm[];
    __half* AS  = sm;                      // [2][128*HLD]
    __half* BGS = sm + 2 * 128 * HLD;      // [2][128*HLD] (n-major)
    __half* BUS = BGS + 2 * 128 * HLD;
    __shared__ int rows[128];

    const int tid  = threadIdx.x;
    const int lane = tid & 31;
    const int wid  = tid >> 5;
    const int warp_m = wid & 3;
    const int warp_n = wid >> 2;

    if (tid < 128) {
        if (GATHER) {
            int i = m0 + tid;
            rows[tid] = g_tok[e * T + (i < cnt ? i : cnt - 1)];
        } else {
            rows[tid] = m0 + tid;
        }
    }
    __syncthreads();

    const int fRow = tid >> 2, fKc = (tid & 3) * 8;
    const __half* aG  = A + (size_t)rows[fRow] * D + fKc;
    const __half* bgG = Bg + (use_expert ? (size_t)e * b_exp_stride : 0) +
                        (size_t)(n0 + fRow) * D + fKc;
    const __half* buG = Bu + (use_expert ? (size_t)e * b_exp_stride : 0) +
                        (size_t)(n0 + fRow) * D + fKc;
    const int fOff = fRow * HLD + fKc;

    const uint32_t aSm  = su32(AS);
    const uint32_t bgSm = su32(BGS);
    const uint32_t buSm = su32(BUS);
    uint32_t aOff[2], bOff[2];
#pragma unroll
    for (int mt = 0; mt < 2; mt++)
        aOff[mt] = ((warp_m * 32 + mt * 16 + (lane & 15)) * HLD +
                    (lane >> 4) * 8) * 2;
#pragma unroll
    for (int p = 0; p < 2; p++)
        bOff[p] = ((warp_n * 32 + p * 16 + (lane >> 4) * 8 + (lane & 7)) * HLD +
                   ((lane >> 3) & 1) * 8) * 2;

    float ag[2][4][4], au[2][4][4];
#pragma unroll
    for (int mt = 0; mt < 2; mt++)
#pragma unroll
        for (int nt = 0; nt < 4; nt++)
#pragma unroll
            for (int j = 0; j < 4; j++) { ag[mt][nt][j] = 0.f; au[mt][nt][j] = 0.f; }

    {   // stage 0 (k 0..63)
        cph16(&AS[fOff], aG);            cph16(&AS[fOff + 32], aG + 32);
        cph16(&BGS[fOff], bgG);          cph16(&BGS[fOff + 32], bgG + 32);
        cph16(&BUS[fOff], buG);          cph16(&BUS[fOff + 32], buG + 32);
    }
    CP_COMMIT();

    int buf = 0;
    for (int k0 = 0; k0 < D; k0 += 64) {
        if (k0 + 64 < D) {
            int s = buf ^ 1;
            const int so = s * 128 * HLD;
            cph16(&AS[so + fOff], aG + k0 + 64);
            cph16(&AS[so + fOff + 32], aG + k0 + 96);
            cph16(&BGS[so + fOff], bgG + k0 + 64);
            cph16(&BGS[so + fOff + 32], bgG + k0 + 96);
            cph16(&BUS[so + fOff], buG + k0 + 64);
            cph16(&BUS[so + fOff + 32], buG + k0 + 96);
        }
        CP_COMMIT();
        CP_WAIT1();
        __syncthreads();

        const uint32_t aB  = aSm  + buf * (128 * HLD * 2);
        const uint32_t bgB = bgSm + buf * (128 * HLD * 2);
        const uint32_t buB = buSm + buf * (128 * HLD * 2);
#pragma unroll
        for (int ks = 0; ks < 4; ks++) {
            const uint32_t kOfs = ks * 32;   // 16 halfs
            uint32_t af[2][4], bfg[4][2], bfu[4][2];
#pragma unroll
            for (int mt = 0; mt < 2; mt++)
                ldm_x4(af[mt][0], af[mt][1], af[mt][2], af[mt][3],
                       aB + aOff[mt] + kOfs);
#pragma unroll
            for (int p = 0; p < 2; p++) {
                ldm_x4(bfg[2 * p][0], bfg[2 * p][1], bfg[2 * p + 1][0],
                       bfg[2 * p + 1][1], bgB + bOff[p] + kOfs);
                ldm_x4(bfu[2 * p][0], bfu[2 * p][1], bfu[2 * p + 1][0],
                       bfu[2 * p + 1][1], buB + bOff[p] + kOfs);
            }
#pragma unroll
            for (int mt = 0; mt < 2; mt++)
#pragma unroll
                for (int nt = 0; nt < 4; nt++) {
                    mma_f16(ag[mt][nt], af[mt], bfg[nt]);
                    mma_f16(au[mt][nt], af[mt], bfu[nt]);
                }
        }
        __syncthreads();
        buf ^= 1;
    }

#pragma unroll
    for (int mt = 0; mt < 2; mt++) {
#pragma unroll
        for (int half = 0; half < 2; half++) {
            const int m = m0 + warp_m * 32 + mt * 16 + (lane >> 2) + half * 8;
            if (m >= cnt) continue;
            __half* orow = use_expert
                ? Oact + ((size_t)e * T + m) * ostride + n0
                : Oact + (size_t)m * ostride + n0;
#pragma unroll
            for (int nt = 0; nt < 4; nt++) {
                const int c = warp_n * 32 + nt * 8 + 2 * (lane & 3);
                float g0 = ag[mt][nt][half * 2 + 0], u0 = au[mt][nt][half * 2 + 0];
                float g1 = ag[mt][nt][half * 2 + 1], u1 = au[mt][nt][half * 2 + 1];
                __half2 o = __floats2half2_rn(silu(g0) * u0, silu(g1) * u1);
                *(__half2*)(orow + c) = o;
            }
        }
    }
}

// ================= down GEMM (tile 128x256, BK=64, 512 thr) ===================
#define EPI_STORE  2
#define EPI_ATOMIC 3

template <int MODE>
__global__ void __launch_bounds__(512, 1)
down_mma(const __half* __restrict__ A, const __half* __restrict__ B,
         float* __restrict__ O, int K, size_t b_exp_stride, int use_expert) {
    const int e   = use_expert ? blockIdx.z : 0;
    const int cnt = use_expert ? g_cnt[e] : T;
    const int m0  = blockIdx.y * 128;
    if (m0 >= cnt) return;
    const int n0  = blockIdx.x * 256;

    extern __shared__ __half sm[];
    __half* AS = sm;                       // [2][128*HLD]
    __half* BS = sm + 2 * 128 * HLD;       // [2][256*HLD] (n-major)

    const int tid  = threadIdx.x;
    const int lane = tid & 31;
    const int wid  = tid >> 5;
    const int warp_m = wid & 3;
    const int warp_n = wid >> 2;

    const int fRow = tid >> 2, fKc = (tid & 3) * 8;
    const int gRow = tid >> 1, gKc = (tid & 1) * 8;
    const int fOff = fRow * HLD + fKc;
    const int gOff = gRow * HLD + gKc;

    const __half* aG = A + (use_expert ? (size_t)e * T * K : 0) +
                       (size_t)(m0 + fRow) * K + fKc;
    const __half* bG = B + (use_expert ? (size_t)e * b_exp_stride : 0) +
                       (size_t)(n0 + gRow) * K + gKc;

    const uint32_t aSm = su32(AS);
    const uint32_t bSm = su32(BS);
    uint32_t aOff[2], bOff[4];
#pragma unroll
    for (int mt = 0; mt < 2; mt++)
        aOff[mt] = ((warp_m * 32 + mt * 16 + (lane & 15)) * HLD +
                    (lane >> 4) * 8) * 2;
#pragma unroll
    for (int p = 0; p < 4; p++)
        bOff[p] = ((warp_n * 64 + p * 16 + (lane >> 4) * 8 + (lane & 7)) * HLD +
                   ((lane >> 3) & 1) * 8) * 2;

    float acc[2][8][4];
#pragma unroll
    for (int mt = 0; mt < 2; mt++)
#pragma unroll
        for (int nt = 0; nt < 8; nt++)
#pragma unroll
            for (int j = 0; j < 4; j++) acc[mt][nt][j] = 0.f;

    {
        cph16(&AS[fOff], aG);           cph16(&AS[fOff + 32], aG + 32);
        cph16(&BS[gOff], bG);           cph16(&BS[gOff + 16], bG + 16);
        cph16(&BS[gOff + 32], bG + 32); cph16(&BS[gOff + 48], bG + 48);
    }
    CP_COMMIT();

    int buf = 0;
    for (int k0 = 0; k0 < K; k0 += 64) {
        if (k0 + 64 < K) {
            int s = buf ^ 1;
            const int ao = s * 128 * HLD, bo = s * 256 * HLD;
            const __half* ap = aG + k0 + 64;
            cph16(&AS[ao + fOff], ap);
            cph16(&AS[ao + fOff + 32], ap + 32);
            const __half* bp = bG + k0 + 64;
            cph16(&BS[bo + gOff], bp);
            cph16(&BS[bo + gOff + 16], bp + 16);
            cph16(&BS[bo + gOff + 32], bp + 32);
            cph16(&BS[bo + gOff + 48], bp + 48);
        }
        CP_COMMIT();
        CP_WAIT1();
        __syncthreads();

        const uint32_t aB = aSm + buf * (128 * HLD * 2);
        const uint32_t bB = bSm + buf * (256 * HLD * 2);
#pragma unroll
        for (int ks = 0; ks < 4; ks++) {
            const uint32_t kOfs = ks * 32;
            uint32_t af[2][4], bf[8][2];
#pragma unroll
            for (int mt = 0; mt < 2; mt++)
                ldm_x4(af[mt][0], af[mt][1], af[mt][2], af[mt][3],
                       aB + aOff[mt] + kOfs);
#pragma unroll
            for (int p = 0; p < 4; p++)
                ldm_x4(bf[2 * p][0], bf[2 * p][1], bf[2 * p + 1][0],
                       bf[2 * p + 1][1], bB + bOff[p] + kOfs);
#pragma unroll
            for (int mt = 0; mt < 2; mt++)
#pragma unroll
                for (int nt = 0; nt < 8; nt++)
                    mma_f16(acc[mt][nt], af[mt], bf[nt]);
        }
        __syncthreads();
        buf ^= 1;
    }

#pragma unroll
    for (int mt = 0; mt < 2; mt++) {
#pragma unroll
        for (int half = 0; half < 2; half++) {
            const int m = m0 + warp_m * 32 + mt * 16 + (lane >> 2) + half * 8;
            if (m >= cnt) continue;
            int   tok = m;
            float w   = 1.f;
            if (MODE == EPI_ATOMIC) { tok = g_tok[e * T + m]; w = g_wt[e * T + m]; }
            float* orow = O + (size_t)tok * D + n0;
#pragma unroll
            for (int nt = 0; nt < 8; nt++) {
                const int c = warp_n * 64 + nt * 8 + 2 * (lane & 3);
                float v0 = acc[mt][nt][half * 2 + 0];
                float v1 = acc[mt][nt][half * 2 + 1];
                if (MODE == EPI_STORE) {
                    float2 o = {v0, v1};
                    *(float2*)(orow + c) = o;
                } else {
                    atomicAdd(orow + c,     w * v0);
                    atomicAdd(orow + c + 1, w * v1);
                }
            }
        }
    }
}

// ---------------- prep kernels --------------------------------------------------
__global__ void zero_cnt_kernel() {
    if (threadIdx.x < E) g_cnt[threadIdx.x] = 0;
}

__global__ void cvtx_kernel(const float* __restrict__ x) {
    size_t i = ((size_t)blockIdx.x * 256 + threadIdx.x) * 4;
    float4 v = *(const float4*)(x + i);
    __half2 h0 = __floats2half2_rn(v.x, v.y);
    __half2 h1 = __floats2half2_rn(v.z, v.w);
    *(__half2*)(g_xh + i)     = h0;
    *(__half2*)(g_xh + i + 2) = h1;
}

__global__ void transpose_h(const float* __restrict__ src, __half* __restrict__ dst,
                            int R, int C) {
    __shared__ float tile[32][33];
    size_t zs = (size_t)blockIdx.z * R * C;
    const int c0 = blockIdx.x * 32, r0 = blockIdx.y * 32;
    const int t = threadIdx.x;
    const int row = t >> 3, cx = (t & 7) * 4;

    float4 v = *(const float4*)(src + zs + (size_t)(r0 + row) * C + c0 + cx);
    tile[cx + 0][row] = v.x; tile[cx + 1][row] = v.y;
    tile[cx + 2][row] = v.z; tile[cx + 3][row] = v.w;
    __syncthreads();

    const int cc = row, rr = cx;
    __half2 h0 = __floats2half2_rn(tile[cc][rr],     tile[cc][rr + 1]);
    __half2 h1 = __floats2half2_rn(tile[cc][rr + 2], tile[cc][rr + 3]);
    uint2 o = {*(uint32_t*)&h0, *(uint32_t*)&h1};
    *(uint2*)(dst + zs + (size_t)(c0 + cc) * R + r0 + rr) = o;
}

__global__ void transpose2_h(const float* __restrict__ sa, const float* __restrict__ sb,
                             __half* __restrict__ da, __half* __restrict__ db,
                             int R, int C) {
    __shared__ float ta[32][33], tb[32][33];
    size_t zs = (size_t)blockIdx.z * R * C;
    const int c0 = blockIdx.x * 32, r0 = blockIdx.y * 32;
    const int t = threadIdx.x;
    const int row = t >> 3, cx = (t & 7) * 4;
    const size_t gi = zs + (size_t)(r0 + row) * C + c0 + cx;

    float4 va = *(const float4*)(sa + gi);
    float4 vb = *(const float4*)(sb + gi);
    ta[cx + 0][row] = va.x; ta[cx + 1][row] = va.y;
    ta[cx + 2][row] = va.z; ta[cx + 3][row] = va.w;
    tb[cx + 0][row] = vb.x; tb[cx + 1][row] = vb.y;
    tb[cx + 2][row] = vb.z; tb[cx + 3][row] = vb.w;
    __syncthreads();

    const int cc = row, rr = cx;
    const size_t go = zs + (size_t)(c0 + cc) * R + r0 + rr;
    __half2 a0 = __floats2half2_rn(ta[cc][rr],     ta[cc][rr + 1]);
    __half2 a1 = __floats2half2_rn(ta[cc][rr + 2], ta[cc][rr + 3]);
    uint2 oa = {*(uint32_t*)&a0, *(uint32_t*)&a1};
    *(uint2*)(da + go) = oa;
    __half2 b0 = __floats2half2_rn(tb[cc][rr],     tb[cc][rr + 1]);
    __half2 b1 = __floats2half2_rn(tb[cc][rr + 2], tb[cc][rr + 3]);
    uint2 ob = {*(uint32_t*)&b0, *(uint32_t*)&b1};
    *(uint2*)(db + go) = ob;
}

// ---------------- router: x register-cached (fp32, bit-exact routing) -----------
__global__ void router_kernel(const float* __restrict__ x,
                              const float* __restrict__ rw,
                              const float* __restrict__ bias) {
    int t    = blockIdx.x * (blockDim.x >> 5) + (threadIdx.x >> 5);
    int lane = threadIdx.x & 31;
    if (t >= T) return;
    const float4* xr = (const float4*)(x + (size_t)t * D);

    // cache this token's x once: 8 float4 per lane (lane-strided, same order)
    float4 xc[8];
#pragma unroll
    for (int i = 0; i < 8; i++) xc[i] = xr[lane + i * 32];

    float logit[E];
#pragma unroll
    for (int e = 0; e < E; e++) {
        const float4* w = (const float4*)(rw + (size_t)e * D);
        float p = 0.f;
#pragma unroll
        for (int i = 0; i < 8; i++) {
            float4 a = xc[i], b = w[lane + i * 32];
            p += a.x * b.x + a.y * b.y + a.z * b.z + a.w * b.w;
        }
#pragma unroll
        for (int o = 16; o > 0; o >>= 1) p += __shfl_xor_sync(0xffffffffu, p, o);
        logit[e] = p;
    }

    if (lane == 0) {
        float scores[E], s[E];
#pragma unroll
        for (int e = 0; e < E; e++) {
            scores[e] = 1.f / (1.f + expf(-logit[e]));
            s[e]      = scores[e] + bias[e];
        }
        float gs[NG];
#pragma unroll
        for (int g = 0; g < NG; g++) {
            float m1 = -1e30f, m2 = -1e30f;
#pragma unroll
            for (int j = 0; j < EPG; j++) {
                float v = s[g * EPG + j];
                if (v > m1) { m2 = m1; m1 = v; }
                else if (v > m2) { m2 = v; }
            }
            gs[g] = m1 + m2;
        }
        int g1 = 0; float b1 = -1e30f;
#pragma unroll
        for (int g = 0; g < NG; g++) if (gs[g] > b1) { b1 = gs[g]; g1 = g; }
        int g2 = -1; float b2 = -1e30f;
#pragma unroll
        for (int g = 0; g < NG; g++) if (g != g1 && gs[g] > b2) { b2 = gs[g]; g2 = g; }

        float masked[E];
#pragma unroll
        for (int e = 0; e < E; e++) {
            int g = e / EPG;
            masked[e] = (g == g1 || g == g2) ? s[e] : -1.0f;
        }
        int idx[KSEL]; bool taken[E];
#pragma unroll
        for (int e = 0; e < E; e++) taken[e] = false;
#pragma unroll
        for (int k = 0; k < KSEL; k++) {
            float best = -1e30f; int bi = 0;
#pragma unroll
            for (int e = 0; e < E; e++)
                if (!taken[e] && masked[e] > best) { best = masked[e]; bi = e; }
            taken[bi] = true;
            idx[k] = bi;
        }
        float tw[KSEL], sum = 0.f;
#pragma unroll
        for (int k = 0; k < KSEL; k++) { tw[k] = scores[idx[k]]; sum += tw[k]; }
        float inv = SCALEF / (sum + 1e-20f);
#pragma unroll
        for (int k = 0; k < KSEL; k++) {
            int e = idx[k];
            int pos = atomicAdd(&g_cnt[e], 1);
            g_tok[e * T + pos] = t;
            g_wt [e * T + pos] = tw[k] * inv;
        }
    }
}

// ---------------- launch --------------------------------------------------------
extern "C" void kernel_launch(void* const* d_in, const int* in_sizes, int n_in,
                              void* d_out, int out_size) {
    const float* x      = (const float*)d_in[0];
    const float* rw     = (const float*)d_in[1];
    const float* bias   = (const float*)d_in[2];
    const float* gate_w = (const float*)d_in[3];   // [E][D][F]
    const float* up_w   = (const float*)d_in[4];   // [E][D][F]
    const float* down_w = (const float*)d_in[5];   // [E][F][D]
    const float* shg    = (const float*)d_in[6];   // [D][SHF]
    const float* shu    = (const float*)d_in[7];   // [D][SHF]
    const float* shd    = (const float*)d_in[8];   // [SHF][D]
    float* out = (float*)d_out;

    __half *p_xh, *p_gwT, *p_uwT, *p_dwT, *p_shgT, *p_shuT, *p_shdT, *p_act, *p_shact;
    cudaGetSymbolAddress((void**)&p_xh,    g_xh);
    cudaGetSymbolAddress((void**)&p_gwT,   g_gwT);
    cudaGetSymbolAddress((void**)&p_uwT,   g_uwT);
    cudaGetSymbolAddress((void**)&p_dwT,   g_dwT);
    cudaGetSymbolAddress((void**)&p_shgT,  g_shgT);
    cudaGetSymbolAddress((void**)&p_shuT,  g_shuT);
    cudaGetSymbolAddress((void**)&p_shdT,  g_shdT);
    cudaGetSymbolAddress((void**)&p_act,   g_act);
    cudaGetSymbolAddress((void**)&p_shact, g_shact);

    cudaFuncSetAttribute(gateup_mma<true>,
                         cudaFuncAttributeMaxDynamicSharedMemorySize, GU_SMEM);
    cudaFuncSetAttribute(gateup_mma<false>,
                         cudaFuncAttributeMaxDynamicSharedMemorySize, GU_SMEM);
    cudaFuncSetAttribute(down_mma<EPI_STORE>,
                         cudaFuncAttributeMaxDynamicSharedMemorySize, DN_SMEM);
    cudaFuncSetAttribute(down_mma<EPI_ATOMIC>,
                         cudaFuncAttributeMaxDynamicSharedMemorySize, DN_SMEM);

    // launch index 5 = routed gateup (ncu -s 5 profiles the GEMM)
    zero_cnt_kernel<<<1, 32>>>();                                        // 0
    cvtx_kernel<<<(T * D) / 1024, 256>>>(x);                             // 1
    transpose2_h<<<dim3(F / 32, D / 32, E), 256>>>(gate_w, up_w,         // 2
                                                   p_gwT, p_uwT, D, F);
    router_kernel<<<T / 8, 256>>>(x, rw, bias);                          // 3
    transpose_h<<<dim3(D / 32, F / 32, E), 256>>>(down_w, p_dwT, F, D);  // 4
    gateup_mma<true><<<dim3(F / 128, T / 128, E), 512, GU_SMEM>>>(       // 5
        p_xh, p_gwT, p_uwT, p_act, (size_t)F * D, F, 1);
    transpose_h<<<dim3(SHF / 32, D / 32,   1), 256>>>(shg, p_shgT, D,   SHF);
    transpose_h<<<dim3(SHF / 32, D / 32,   1), 256>>>(shu, p_shuT, D,   SHF);
    transpose_h<<<dim3(D / 32,   SHF / 32, 1), 256>>>(shd, p_shdT, SHF, D);
    gateup_mma<false><<<dim3(SHF / 128, T / 128, 1), 512, GU_SMEM>>>(
        p_xh, p_shgT, p_shuT, p_shact, 0, SHF, 0);
    down_mma<EPI_STORE><<<dim3(D / 256, T / 128, 1), 512, DN_SMEM>>>(
        p_shact, p_shdT, out, SHF, 0, 0);
    down_mma<EPI_ATOMIC><<<dim3(D / 256, T / 128, E), 512, DN_SMEM>>>(
        p_act, p_dwT, out, F, (size_t)F * D, 1);
}